// round 14
// baseline (speedup 1.0000x reference)
#include <cuda_runtime.h>
#include <cuda_fp16.h>
#include <math.h>
#include <stdint.h>

#define Bsz 1024
#define TT  730
#define INN 64
#define HH  512
#define KK  576
#define G4  2048

#define BM 128
#define BN 128
#define NCHUNK 9
#define GROUP_CTAS 16              // CTAs per mt-group (all nt)
#define NTHREADS 512

#define CHUNK_B 16384              // 128 rows x 128 B
#define B_RES_B (NCHUNK * CHUNK_B) // 147456: resident weights
#define A_STG_B (4 * CHUNK_B)      // 65536: 4-stage A pipeline
#define SMEM_BYTES (B_RES_B + A_STG_B)   // 212992

// ---- device-global scratch (allocation-free) ----
__device__ __half g_Wc[(size_t)G4 * KK];          // [colpos][k] fp16
__device__ float  g_bias4[HH * 4];                // [h][gate]
__device__ __half g_x16[(size_t)TT * Bsz * INN];  // [t][b][k] fp16
__device__ __half g_h[2][Bsz * HH];               // hidden state
__device__ unsigned g_barr[8];                    // per-mt group barrier counters

__device__ __forceinline__ unsigned h2_as_u32(__half2 h) {
    union { __half2 h; unsigned u; } cvt;
    cvt.h = h;
    return cvt.u;
}
__device__ __forceinline__ uint32_t smem_u32(const void* p) {
    return (uint32_t)__cvta_generic_to_shared(p);
}
__device__ __forceinline__ void cpa16s(uint32_t dst, const void* src) {
    asm volatile("cp.async.cg.shared.global [%0], [%1], 16;" :: "r"(dst), "l"(src));
}
#define CP_COMMIT() asm volatile("cp.async.commit_group;")
#define CP_WAIT(n)  asm volatile("cp.async.wait_group %0;" :: "n"(n) : "memory")

#define LDSM4(r, a)                                                           \
    asm volatile("ldmatrix.sync.aligned.m8n8.x4.shared.b16 {%0,%1,%2,%3}, [%4];" \
        : "=r"((r)[0]), "=r"((r)[1]), "=r"((r)[2]), "=r"((r)[3]) : "r"(a))

#define MMA_F16(d, a, b)                                                      \
    asm volatile(                                                             \
        "mma.sync.aligned.m16n8k16.row.col.f32.f16.f16.f32 "                  \
        "{%0,%1,%2,%3}, {%4,%5,%6,%7}, {%8,%9}, {%0,%1,%2,%3};"               \
        : "+f"((d)[0]), "+f"((d)[1]), "+f"((d)[2]), "+f"((d)[3])              \
        : "r"((a)[0]), "r"((a)[1]), "r"((a)[2]), "r"((a)[3]),                 \
          "r"((b)[0]), "r"((b)[1]))

// ---------------- prep (unchanged from R13) ----------------
__global__ void prep_w_kernel(const float* __restrict__ Wih,
                              const float* __restrict__ Whh,
                              const float* __restrict__ bias) {
    int idx = blockIdx.x * blockDim.x + threadIdx.x;
    if (idx >= G4 * KK) return;
    int p = idx / KK;
    int k = idx % KK;
    int nt = p >> 7, loc = p & 127;
    int wn = loc >> 5, g = (loc >> 3) & 3, hl = loc & 7;
    int h = nt * 32 + wn * 8 + hl;
    int w = g * HH + h;
    float v = (k < INN) ? Wih[(size_t)w * INN + k]
                        : Whh[(size_t)w * HH + (k - INN)];
    g_Wc[idx] = __float2half(v);
    if (idx < HH * 4) {
        int hh = idx >> 2, gg = idx & 3;
        g_bias4[idx] = bias[gg * HH + hh];
    }
}

__global__ void prep_x_kernel(const float* __restrict__ xd) {
    size_t idx = (size_t)blockIdx.x * blockDim.x + threadIdx.x;
    if (idx >= (size_t)TT * Bsz * INN) return;
    int k = (int)(idx & 63);
    int b = (int)((idx >> 6) & 1023);
    int t = (int)(idx >> 16);
    g_x16[idx] = __float2half(xd[(size_t)b * TT * INN + (size_t)t * INN + k]);
}

__global__ void zero_kernel() {
    int idx = blockIdx.x * blockDim.x + threadIdx.x;
    if (idx < Bsz * HH) g_h[0][idx] = __float2half(0.0f);
    if (idx < 8) g_barr[idx] = 0;
}

__device__ __forceinline__ float tanh_ap(float x) {
    float r;
    asm("tanh.approx.f32 %0, %1;" : "=f"(r) : "f"(x));
    return r;
}
__device__ __forceinline__ float sig_ap(float x) {
    return fmaf(0.5f, tanh_ap(0.5f * x), 0.5f);
}

// ---------------- persistent LSTM (512 threads, 32x32 warp tiles) ----------------
__global__ __launch_bounds__(NTHREADS, 1)
void lstm_persist_kernel() {
    extern __shared__ char smem[];
    const uint32_t sbase = smem_u32(smem);
    const uint32_t BresS = sbase;               // 9 x 16KB resident weights
    const uint32_t AstgS = sbase + B_RES_B;     // 4 x 16KB A stages

    const int tid  = threadIdx.x;
    const int lane = tid & 31;
    const int wid  = tid >> 5;
    const int grp  = lane >> 2;
    const int tig  = lane & 3;
    const int wm   = wid & 3;        // 4 warps over M (32 rows each)
    const int wn   = wid >> 2;       // 4 warps over N (32 cols each)

    const int nt = blockIdx.x, mt = blockIdx.y;
    const int n0 = nt * BN, b0 = mt * BM;

    // ---- resident B load (once) ----
#pragma unroll
    for (int i = 0; i < 18; i++) {
        int u = i * NTHREADS + tid;
        int kc  = u >> 10;
        int rem = u & 1023;
        int c = rem >> 3, cq = rem & 7;
        cpa16s(BresS + kc * CHUNK_B + c * 128 + ((cq ^ (c & 7)) << 4),
               g_Wc + (size_t)(n0 + c) * KK + kc * 64 + cq * 8);
    }
    CP_COMMIT();

    // ---- per-lane ldmatrix address constants ----
    const int l7 = lane & 7;
    const uint32_t rAoff = (uint32_t)(wm * 32 + ((lane >> 3) & 1) * 8 + l7) * 128;
    const int kA = (lane >> 4) & 1;
    const uint32_t rBoff = (uint32_t)(wn * 32 + ((lane >> 4) & 1) * 8 + l7) * 128;
    const int kB = (lane >> 3) & 1;
    uint32_t swA[4], swB[4];
#pragma unroll
    for (int ks = 0; ks < 4; ks++) {
        swA[ks] = (uint32_t)(((ks * 2 + kA) ^ l7) << 4);
        swB[ks] = (uint32_t)(((ks * 2 + kB) ^ l7) << 4);
    }

    auto load_x = [&](int t, int stage) {
        uint32_t Ab = AstgS + stage * CHUNK_B;
#pragma unroll
        for (int i = 0; i < 2; i++) {
            int u = i * NTHREADS + tid;
            int r = u >> 3, cq = u & 7;
            cpa16s(Ab + r * 128 + ((cq ^ (r & 7)) << 4),
                   g_x16 + ((size_t)t * Bsz + b0 + r) * INN + cq * 8);
        }
        CP_COMMIT();
    };
    auto load_h = [&](const __half* hp, int kc, int stage) {   // kc in 1..8
        uint32_t Ab = AstgS + stage * CHUNK_B;
#pragma unroll
        for (int i = 0; i < 2; i++) {
            int u = i * NTHREADS + tid;
            int r = u >> 3, cq = u & 7;
            cpa16s(Ab + r * 128 + ((cq ^ (r & 7)) << 4),
                   hp + ((size_t)(b0 + r) << 9) + (kc - 1) * 64 + cq * 8);
        }
        CP_COMMIT();
    };

    // fragment slice loader (A + B of k16 slice ks)
    auto ldsm_slice = [&](uint32_t Ab, uint32_t Bb, int ks,
                          unsigned (*a)[4], unsigned (*b)[2]) {
#pragma unroll
        for (int mf = 0; mf < 2; mf++)
            LDSM4(a[mf], Ab + rAoff + mf * 2048 + swA[ks]);
        unsigned r01[4], r23[4];
        LDSM4(r01, Bb + rBoff + swB[ks]);
        LDSM4(r23, Bb + rBoff + 2048 + swB[ks]);
        b[0][0] = r01[0]; b[0][1] = r01[1];
        b[1][0] = r01[2]; b[1][1] = r01[3];
        b[2][0] = r23[0]; b[2][1] = r23[1];
        b[3][0] = r23[2]; b[3][1] = r23[3];
    };

    // prologue (t=0): x0 -> stage0, h1 -> stage1, h2 -> stage2
    load_x(0, 0);
    load_h(g_h[0], 1, 1);
    load_h(g_h[0], 2, 2);
    CP_WAIT(2);            // B resident + x0 complete
    __syncthreads();

    unsigned f0a[2][4], f0b[4][2], f1a[2][4], f1b[4][2];
    ldsm_slice(AstgS + 0 * CHUNK_B, BresS + 0 * CHUNK_B, 0, f0a, f0b);  // chunk0 slice0

    const int qh = nt * 32 + wn * 8 + tig * 2;
    const float4 bg0 = *(const float4*)&g_bias4[qh * 4];
    const float4 bg1 = *(const float4*)&g_bias4[(qh + 1) * 4];

    float creg[2][2][2];
#pragma unroll
    for (int mf = 0; mf < 2; mf++)
#pragma unroll
        for (int rr = 0; rr < 2; rr++) {
            creg[mf][rr][0] = 0.0f;
            creg[mf][rr][1] = 0.0f;
        }

#pragma unroll 1
    for (int t = 0; t < TT; t++) {
        const __half* __restrict__ hprev = g_h[t & 1];
        __half* __restrict__ hnew = g_h[(t & 1) ^ 1];

        float acc[2][4][4];
#pragma unroll
        for (int mf = 0; mf < 2; mf++)
#pragma unroll
            for (int nf = 0; nf < 4; nf++)
#pragma unroll
                for (int r = 0; r < 4; r++) acc[mf][nf][r] = 0.0f;

#pragma unroll 1
        for (int kc = 0; kc < NCHUNK; kc++) {
            // top: issue next A loads (stage kc+3) / cross-step x prefetch
            if (kc < 6) {
                load_h(hprev, kc + 3, (t + kc + 3) & 3);
            } else if (kc == 6) {
                load_x(t + 1 < TT ? t + 1 : 0, (t + 9) & 3);
            }

            const uint32_t Ab = AstgS + ((t + kc) & 3) * CHUNK_B;
            const uint32_t Bb = BresS + kc * CHUNK_B;

            // f0 holds slice0 of this chunk (prefetched at previous tail)
            ldsm_slice(Ab, Bb, 1, f1a, f1b);
#pragma unroll
            for (int mf = 0; mf < 2; mf++)
#pragma unroll
                for (int nf = 0; nf < 4; nf++)
                    MMA_F16(acc[mf][nf], f0a[mf], f0b[nf]);
            ldsm_slice(Ab, Bb, 2, f0a, f0b);
#pragma unroll
            for (int mf = 0; mf < 2; mf++)
#pragma unroll
                for (int nf = 0; nf < 4; nf++)
                    MMA_F16(acc[mf][nf], f1a[mf], f1b[nf]);
            ldsm_slice(Ab, Bb, 3, f1a, f1b);
#pragma unroll
            for (int mf = 0; mf < 2; mf++)
#pragma unroll
                for (int nf = 0; nf < 4; nf++)
                    MMA_F16(acc[mf][nf], f0a[mf], f0b[nf]);

            // tail: sync for next stage, prefetch next chunk slice0, then slice3 MMAs
            if (kc < 8) {
                if (kc == 7) CP_WAIT(1); else CP_WAIT(2);
                __syncthreads();
                ldsm_slice(AstgS + ((t + kc + 1) & 3) * CHUNK_B,
                           BresS + (kc + 1) * CHUNK_B, 0, f0a, f0b);
            } else {
                CP_WAIT(0);          // x stage for next step complete
                __syncthreads();
                ldsm_slice(AstgS + ((t + 1) & 3) * CHUNK_B,
                           BresS + 0 * CHUNK_B, 0, f0a, f0b);
            }
#pragma unroll
            for (int mf = 0; mf < 2; mf++)
#pragma unroll
                for (int nf = 0; nf < 4; nf++)
                    MMA_F16(acc[mf][nf], f1a[mf], f1b[nf]);
        }

        // ---- register epilogue (c resident, tanh.approx gates) ----
#pragma unroll
        for (int mf = 0; mf < 2; mf++) {
#pragma unroll
            for (int rr = 0; rr < 2; rr++) {
                int b = b0 + wm * 32 + mf * 16 + grp + rr * 8;
                size_t cidx = (size_t)b * HH + qh;
                float hh0, hh1;
                {
                    int j = rr * 2 + 0;
                    float zi = acc[mf][0][j] + bg0.x;
                    float zf = acc[mf][1][j] + bg0.y;
                    float zg = acc[mf][2][j] + bg0.z;
                    float zo = acc[mf][3][j] + bg0.w;
                    float cn = fmaf(sig_ap(zf), creg[mf][rr][0], sig_ap(zi) * tanh_ap(zg));
                    creg[mf][rr][0] = cn;
                    hh0 = sig_ap(zo) * tanh_ap(cn);
                }
                {
                    int j = rr * 2 + 1;
                    float zi = acc[mf][0][j] + bg1.x;
                    float zf = acc[mf][1][j] + bg1.y;
                    float zg = acc[mf][2][j] + bg1.z;
                    float zo = acc[mf][3][j] + bg1.w;
                    float cn = fmaf(sig_ap(zf), creg[mf][rr][1], sig_ap(zi) * tanh_ap(zg));
                    creg[mf][rr][1] = cn;
                    hh1 = sig_ap(zo) * tanh_ap(cn);
                }
                *(unsigned*)&hnew[cidx] = h2_as_u32(__floats2half2_rn(hh0, hh1));
            }
        }

        // ---- mt-group barrier ----
        __threadfence();
        __syncthreads();
        if (tid == 0) {
            atomicAdd(&g_barr[mt], 1u);
            unsigned target = (unsigned)GROUP_CTAS * (unsigned)(t + 1);
            while (*(volatile unsigned*)&g_barr[mt] < target) { }
        }
        __syncthreads();

        if (t + 1 < TT) {
            const __half* hp2 = g_h[(t + 1) & 1];
            load_h(hp2, 1, (t + 2) & 3);
            load_h(hp2, 2, (t + 3) & 3);
        }
    }
}

// out[b] = relu(dot(h_T[b,:], Wl) + bl)
__global__ void head_kernel(const float* __restrict__ Wl,
                            const float* __restrict__ bl,
                            float* __restrict__ out, int sel) {
    int b = blockIdx.x;
    const __half* __restrict__ h = g_h[sel] + (size_t)b * HH;
    float s = 0.0f;
    for (int i = threadIdx.x; i < HH; i += blockDim.x)
        s += __half2float(h[i]) * Wl[i];
#pragma unroll
    for (int o = 16; o; o >>= 1) s += __shfl_down_sync(0xffffffffu, s, o);
    __shared__ float red[8];
    if ((threadIdx.x & 31) == 0) red[threadIdx.x >> 5] = s;
    __syncthreads();
    if (threadIdx.x < 32) {
        s = (threadIdx.x < (blockDim.x >> 5)) ? red[threadIdx.x] : 0.0f;
#pragma unroll
        for (int o = 4; o; o >>= 1) s += __shfl_down_sync(0xffffffffu, s, o);
        if (threadIdx.x == 0) out[b] = fmaxf(s + bl[0], 0.0f);
    }
}

extern "C" void kernel_launch(void* const* d_in, const int* in_sizes, int n_in,
                              void* d_out, int out_size) {
    const float* xd   = (const float*)d_in[0];
    const float* Wih  = (const float*)d_in[1];
    const float* Whh  = (const float*)d_in[2];
    const float* bias = (const float*)d_in[3];
    const float* Wl   = (const float*)d_in[4];
    const float* bl   = (const float*)d_in[5];
    float* out = (float*)d_out;

    cudaFuncSetAttribute(lstm_persist_kernel,
                         cudaFuncAttributeMaxDynamicSharedMemorySize, SMEM_BYTES);

    prep_w_kernel<<<(G4 * KK + 255) / 256, 256>>>(Wih, Whh, bias);
    {
        size_t nx = (size_t)TT * Bsz * INN;
        prep_x_kernel<<<(unsigned)((nx + 255) / 256), 256>>>(xd);
    }
    zero_kernel<<<(Bsz * HH + 255) / 256, 256>>>();

    lstm_persist_kernel<<<dim3(G4 / BN, Bsz / BM), NTHREADS, SMEM_BYTES>>>();

    head_kernel<<<Bsz, 256>>>(Wl, bl, out, 0);
}

// round 15
// speedup vs baseline: 1.1012x; 1.1012x over previous
#include <cuda_runtime.h>
#include <cuda_fp16.h>
#include <math.h>
#include <stdint.h>

#define Bsz 1024
#define TT  730
#define INN 64
#define HH  512
#define KK  576
#define G4  2048

#define BM 128
#define BN 128
#define NCHUNK 9
#define GROUP_CTAS 16              // CTAs per mt-group (all nt)
#define NTHREADS 256

#define CHUNK_B 16384              // 128 rows x 128 B
#define B_RES_B (NCHUNK * CHUNK_B) // 147456: resident weights
#define A_STG_B (4 * CHUNK_B)      // 65536: 4-stage A pipeline
#define SMEM_BYTES (B_RES_B + A_STG_B)   // 212992

// ---- device-global scratch (allocation-free) ----
__device__ __half g_Wc[(size_t)G4 * KK];          // [colpos][k] fp16
__device__ float  g_bias4[HH * 4];                // [h][gate]
__device__ __half g_x16[(size_t)TT * Bsz * INN];  // [t][b][k] fp16
__device__ __half g_h[2][Bsz * HH];               // hidden state
__device__ unsigned g_barr[8];                    // per-mt group barrier counters

__device__ __forceinline__ unsigned h2_as_u32(__half2 h) {
    union { __half2 h; unsigned u; } cvt;
    cvt.h = h;
    return cvt.u;
}
__device__ __forceinline__ uint32_t smem_u32(const void* p) {
    return (uint32_t)__cvta_generic_to_shared(p);
}
__device__ __forceinline__ void cpa16s(uint32_t dst, const void* src) {
    asm volatile("cp.async.cg.shared.global [%0], [%1], 16;" :: "r"(dst), "l"(src));
}
#define CP_COMMIT() asm volatile("cp.async.commit_group;")
#define CP_WAIT(n)  asm volatile("cp.async.wait_group %0;" :: "n"(n) : "memory")

#define LDSM4(r, a)                                                           \
    asm volatile("ldmatrix.sync.aligned.m8n8.x4.shared.b16 {%0,%1,%2,%3}, [%4];" \
        : "=r"((r)[0]), "=r"((r)[1]), "=r"((r)[2]), "=r"((r)[3]) : "r"(a))

#define MMA_F16(d, a, b)                                                      \
    asm volatile(                                                             \
        "mma.sync.aligned.m16n8k16.row.col.f32.f16.f16.f32 "                  \
        "{%0,%1,%2,%3}, {%4,%5,%6,%7}, {%8,%9}, {%0,%1,%2,%3};"               \
        : "+f"((d)[0]), "+f"((d)[1]), "+f"((d)[2]), "+f"((d)[3])              \
        : "r"((a)[0]), "r"((a)[1]), "r"((a)[2]), "r"((a)[3]),                 \
          "r"((b)[0]), "r"((b)[1]))

// ---------------- prep (unchanged) ----------------
__global__ void prep_w_kernel(const float* __restrict__ Wih,
                              const float* __restrict__ Whh,
                              const float* __restrict__ bias) {
    int idx = blockIdx.x * blockDim.x + threadIdx.x;
    if (idx >= G4 * KK) return;
    int p = idx / KK;
    int k = idx % KK;
    int nt = p >> 7, loc = p & 127;
    int wn = loc >> 5, g = (loc >> 3) & 3, hl = loc & 7;
    int h = nt * 32 + wn * 8 + hl;
    int w = g * HH + h;
    float v = (k < INN) ? Wih[(size_t)w * INN + k]
                        : Whh[(size_t)w * HH + (k - INN)];
    g_Wc[idx] = __float2half(v);
    if (idx < HH * 4) {
        int hh = idx >> 2, gg = idx & 3;
        g_bias4[idx] = bias[gg * HH + hh];
    }
}

__global__ void prep_x_kernel(const float* __restrict__ xd) {
    size_t idx = (size_t)blockIdx.x * blockDim.x + threadIdx.x;
    if (idx >= (size_t)TT * Bsz * INN) return;
    int k = (int)(idx & 63);
    int b = (int)((idx >> 6) & 1023);
    int t = (int)(idx >> 16);
    g_x16[idx] = __float2half(xd[(size_t)b * TT * INN + (size_t)t * INN + k]);
}

__global__ void zero_kernel() {
    int idx = blockIdx.x * blockDim.x + threadIdx.x;
    if (idx < Bsz * HH) g_h[0][idx] = __float2half(0.0f);
    if (idx < 8) g_barr[idx] = 0;
}

__device__ __forceinline__ float tanh_ap(float x) {
    float r;
    asm("tanh.approx.f32 %0, %1;" : "=f"(r) : "f"(x));
    return r;
}
__device__ __forceinline__ float sig_ap(float x) {
    return fmaf(0.5f, tanh_ap(0.5f * x), 0.5f);
}

// ---------------- persistent LSTM (256 threads, triple-buffered frags) ----------------
__global__ __launch_bounds__(NTHREADS, 1)
void lstm_persist_kernel() {
    extern __shared__ char smem[];
    const uint32_t sbase = smem_u32(smem);
    const uint32_t BresS = sbase;               // 9 x 16KB resident weights
    const uint32_t AstgS = sbase + B_RES_B;     // 4 x 16KB A stages

    const int tid  = threadIdx.x;
    const int lane = tid & 31;
    const int wid  = tid >> 5;
    const int grp  = lane >> 2;
    const int tig  = lane & 3;
    const int wm   = wid & 1;        // 2 warps over M (64 rows each)
    const int wn   = wid >> 1;       // 4 warps over N (32 cols each)

    const int nt = blockIdx.x, mt = blockIdx.y;
    const int n0 = nt * BN, b0 = mt * BM;

    // ---- resident B load (once) ----
#pragma unroll
    for (int i = 0; i < 36; i++) {
        int u = i * NTHREADS + tid;
        int kc  = u >> 10;
        int rem = u & 1023;
        int c = rem >> 3, cq = rem & 7;
        cpa16s(BresS + kc * CHUNK_B + c * 128 + ((cq ^ (c & 7)) << 4),
               g_Wc + (size_t)(n0 + c) * KK + kc * 64 + cq * 8);
    }
    CP_COMMIT();

    // ---- per-lane ldmatrix address constants ----
    const int l7 = lane & 7;
    const uint32_t rAoff = (uint32_t)(wm * 64 + ((lane >> 3) & 1) * 8 + l7) * 128;
    const int kA = (lane >> 4) & 1;
    const uint32_t rBoff = (uint32_t)(wn * 32 + ((lane >> 4) & 1) * 8 + l7) * 128;
    const int kB = (lane >> 3) & 1;
    uint32_t swA[4], swB[4];
#pragma unroll
    for (int ks = 0; ks < 4; ks++) {
        swA[ks] = (uint32_t)(((ks * 2 + kA) ^ l7) << 4);
        swB[ks] = (uint32_t)(((ks * 2 + kB) ^ l7) << 4);
    }

    auto load_x = [&](int t, int stage) {
        uint32_t Ab = AstgS + stage * CHUNK_B;
#pragma unroll
        for (int i = 0; i < 4; i++) {
            int u = i * NTHREADS + tid;
            int r = u >> 3, cq = u & 7;
            cpa16s(Ab + r * 128 + ((cq ^ (r & 7)) << 4),
                   g_x16 + ((size_t)t * Bsz + b0 + r) * INN + cq * 8);
        }
        CP_COMMIT();
    };
    auto load_h = [&](const __half* hp, int kc, int stage) {   // kc in 1..8
        uint32_t Ab = AstgS + stage * CHUNK_B;
#pragma unroll
        for (int i = 0; i < 4; i++) {
            int u = i * NTHREADS + tid;
            int r = u >> 3, cq = u & 7;
            cpa16s(Ab + r * 128 + ((cq ^ (r & 7)) << 4),
                   hp + ((size_t)(b0 + r) << 9) + (kc - 1) * 64 + cq * 8);
        }
        CP_COMMIT();
    };

    // fragment slice loader (A + B of k16 slice ks)
    auto ldsm_slice = [&](uint32_t Ab, uint32_t Bb, int ks,
                          unsigned (*a)[4], unsigned (*b)[2]) {
#pragma unroll
        for (int mf = 0; mf < 4; mf++)
            LDSM4(a[mf], Ab + rAoff + mf * 2048 + swA[ks]);
        unsigned r01[4], r23[4];
        LDSM4(r01, Bb + rBoff + swB[ks]);
        LDSM4(r23, Bb + rBoff + 2048 + swB[ks]);
        b[0][0] = r01[0]; b[0][1] = r01[1];
        b[1][0] = r01[2]; b[1][1] = r01[3];
        b[2][0] = r23[0]; b[2][1] = r23[1];
        b[3][0] = r23[2]; b[3][1] = r23[3];
    };

    // prologue (t=0): x0 -> stage0, h1 -> stage1, h2 -> stage2
    load_x(0, 0);
    load_h(g_h[0], 1, 1);
    load_h(g_h[0], 2, 2);
    CP_WAIT(2);            // B resident + x0 complete
    __syncthreads();

    // triple-buffered fragments: buffer index = global slice % 3
    unsigned fa[3][4][4], fb[3][4][2];
    ldsm_slice(AstgS, BresS, 0, fa[0], fb[0]);   // step0 chunk0 slice0
    ldsm_slice(AstgS, BresS, 1, fa[1], fb[1]);   // step0 chunk0 slice1

    const int qh = nt * 32 + wn * 8 + tig * 2;
    const float4 bg0 = *(const float4*)&g_bias4[qh * 4];
    const float4 bg1 = *(const float4*)&g_bias4[(qh + 1) * 4];

    float creg[4][2][2];
#pragma unroll
    for (int mf = 0; mf < 4; mf++)
#pragma unroll
        for (int rr = 0; rr < 2; rr++) {
            creg[mf][rr][0] = 0.0f;
            creg[mf][rr][1] = 0.0f;
        }

#pragma unroll 1
    for (int t = 0; t < TT; t++) {
        const __half* __restrict__ hprev = g_h[t & 1];
        __half* __restrict__ hnew = g_h[(t & 1) ^ 1];

        float acc[4][4][4];
#pragma unroll
        for (int mf = 0; mf < 4; mf++)
#pragma unroll
            for (int nf = 0; nf < 4; nf++)
#pragma unroll
                for (int r = 0; r < 4; r++) acc[mf][nf][r] = 0.0f;

#pragma unroll
        for (int kc = 0; kc < NCHUNK; kc++) {
            // top-of-chunk cp.async issue
            if (kc < 6) {
                load_h(hprev, kc + 3, (t + kc + 3) & 3);
            } else if (kc == 6) {
                load_x(t + 1 < TT ? t + 1 : 0, (t + 9) & 3);
            }
#pragma unroll
            for (int ks = 0; ks < 4; ks++) {
                const int g = 4 * kc + ks;     // global slice 0..35 (constant)
                const int p = g + 2;           // prefetch target slice
                if (p < 36) {
                    const int kcp = p >> 2, ksp = p & 3;
                    if (ksp == 0) {            // entering new chunk's stage
                        if (kcp < 8) CP_WAIT(2); else CP_WAIT(1);
                        __syncthreads();
                    }
                    ldsm_slice(AstgS + ((t + kcp) & 3) * CHUNK_B,
                               BresS + kcp * CHUNK_B, ksp,
                               fa[p % 3], fb[p % 3]);
                } else {
                    if (p == 36) { CP_WAIT(0); __syncthreads(); }
                    ldsm_slice(AstgS + ((t + 1) & 3) * CHUNK_B,
                               BresS, p - 36,
                               fa[p % 3], fb[p % 3]);
                }
                const int c = g % 3;
#pragma unroll
                for (int mf = 0; mf < 4; mf++)
#pragma unroll
                    for (int nf = 0; nf < 4; nf++)
                        MMA_F16(acc[mf][nf], fa[c][mf], fb[c][nf]);
            }
        }

        // ---- register epilogue (c resident, tanh.approx gates) ----
#pragma unroll
        for (int mf = 0; mf < 4; mf++) {
#pragma unroll
            for (int rr = 0; rr < 2; rr++) {
                int b = b0 + wm * 64 + mf * 16 + grp + rr * 8;
                size_t cidx = (size_t)b * HH + qh;
                float hh0, hh1;
                {
                    int j = rr * 2 + 0;
                    float zi = acc[mf][0][j] + bg0.x;
                    float zf = acc[mf][1][j] + bg0.y;
                    float zg = acc[mf][2][j] + bg0.z;
                    float zo = acc[mf][3][j] + bg0.w;
                    float cn = fmaf(sig_ap(zf), creg[mf][rr][0], sig_ap(zi) * tanh_ap(zg));
                    creg[mf][rr][0] = cn;
                    hh0 = sig_ap(zo) * tanh_ap(cn);
                }
                {
                    int j = rr * 2 + 1;
                    float zi = acc[mf][0][j] + bg1.x;
                    float zf = acc[mf][1][j] + bg1.y;
                    float zg = acc[mf][2][j] + bg1.z;
                    float zo = acc[mf][3][j] + bg1.w;
                    float cn = fmaf(sig_ap(zf), creg[mf][rr][1], sig_ap(zi) * tanh_ap(zg));
                    creg[mf][rr][1] = cn;
                    hh1 = sig_ap(zo) * tanh_ap(cn);
                }
                *(unsigned*)&hnew[cidx] = h2_as_u32(__floats2half2_rn(hh0, hh1));
            }
        }

        // ---- mt-group barrier ----
        __threadfence();
        __syncthreads();
        if (tid == 0) {
            atomicAdd(&g_barr[mt], 1u);
            unsigned target = (unsigned)GROUP_CTAS * (unsigned)(t + 1);
            while (*(volatile unsigned*)&g_barr[mt] < target) { }
        }
        __syncthreads();

        // post-barrier: first h chunks of next step
        if (t + 1 < TT) {
            const __half* hp2 = g_h[(t + 1) & 1];
            load_h(hp2, 1, (t + 2) & 3);
            load_h(hp2, 2, (t + 3) & 3);
        }
    }
}

// out[b] = relu(dot(h_T[b,:], Wl) + bl)
__global__ void head_kernel(const float* __restrict__ Wl,
                            const float* __restrict__ bl,
                            float* __restrict__ out, int sel) {
    int b = blockIdx.x;
    const __half* __restrict__ h = g_h[sel] + (size_t)b * HH;
    float s = 0.0f;
    for (int i = threadIdx.x; i < HH; i += blockDim.x)
        s += __half2float(h[i]) * Wl[i];
#pragma unroll
    for (int o = 16; o; o >>= 1) s += __shfl_down_sync(0xffffffffu, s, o);
    __shared__ float red[8];
    if ((threadIdx.x & 31) == 0) red[threadIdx.x >> 5] = s;
    __syncthreads();
    if (threadIdx.x < 32) {
        s = (threadIdx.x < (blockDim.x >> 5)) ? red[threadIdx.x] : 0.0f;
#pragma unroll
        for (int o = 4; o; o >>= 1) s += __shfl_down_sync(0xffffffffu, s, o);
        if (threadIdx.x == 0) out[b] = fmaxf(s + bl[0], 0.0f);
    }
}

extern "C" void kernel_launch(void* const* d_in, const int* in_sizes, int n_in,
                              void* d_out, int out_size) {
    const float* xd   = (const float*)d_in[0];
    const float* Wih  = (const float*)d_in[1];
    const float* Whh  = (const float*)d_in[2];
    const float* bias = (const float*)d_in[3];
    const float* Wl   = (const float*)d_in[4];
    const float* bl   = (const float*)d_in[5];
    float* out = (float*)d_out;

    cudaFuncSetAttribute(lstm_persist_kernel,
                         cudaFuncAttributeMaxDynamicSharedMemorySize, SMEM_BYTES);

    prep_w_kernel<<<(G4 * KK + 255) / 256, 256>>>(Wih, Whh, bias);
    {
        size_t nx = (size_t)TT * Bsz * INN;
        prep_x_kernel<<<(unsigned)((nx + 255) / 256), 256>>>(xd);
    }
    zero_kernel<<<(Bsz * HH + 255) / 256, 256>>>();

    lstm_persist_kernel<<<dim3(G4 / BN, Bsz / BM), NTHREADS, SMEM_BYTES>>>();

    head_kernel<<<Bsz, 256>>>(Wl, bl, out, 0);
}

// round 16
// speedup vs baseline: 1.1047x; 1.0031x over previous
#include <cuda_runtime.h>
#include <cuda_fp16.h>
#include <math.h>
#include <stdint.h>

#define Bsz 1024
#define TT  730
#define INN 64
#define HH  512
#define KK  576
#define G4  2048

#define BM 128
#define BN 128
#define NCHUNK 9
#define GROUP_CTAS 16
#define NTHREADS 256

#define CHUNK_B 16384
#define B_RES_B (NCHUNK * CHUNK_B)
#define A_STG_B (4 * CHUNK_B)
#define SMEM_BYTES (B_RES_B + A_STG_B)   // 212992

__device__ __half g_Wc[(size_t)G4 * KK];
__device__ float  g_bias4[HH * 4];
__device__ __half g_x16[(size_t)TT * Bsz * INN];
__device__ __half g_h[2][Bsz * HH];
__device__ unsigned g_barr[8];

__device__ __forceinline__ unsigned h2_as_u32(__half2 h) {
    union { __half2 h; unsigned u; } cvt;
    cvt.h = h;
    return cvt.u;
}
__device__ __forceinline__ uint32_t smem_u32(const void* p) {
    return (uint32_t)__cvta_generic_to_shared(p);
}
__device__ __forceinline__ void cpa16s(uint32_t dst, const void* src) {
    asm volatile("cp.async.cg.shared.global [%0], [%1], 16;" :: "r"(dst), "l"(src));
}
#define CP_COMMIT() asm volatile("cp.async.commit_group;")
#define CP_WAIT(n)  asm volatile("cp.async.wait_group %0;" :: "n"(n) : "memory")

#define LDSM4(r, a)                                                           \
    asm volatile("ldmatrix.sync.aligned.m8n8.x4.shared.b16 {%0,%1,%2,%3}, [%4];" \
        : "=r"((r)[0]), "=r"((r)[1]), "=r"((r)[2]), "=r"((r)[3]) : "r"(a))

#define MMA_F16(d, a, b)                                                      \
    asm volatile(                                                             \
        "mma.sync.aligned.m16n8k16.row.col.f32.f16.f16.f32 "                  \
        "{%0,%1,%2,%3}, {%4,%5,%6,%7}, {%8,%9}, {%0,%1,%2,%3};"               \
        : "+f"((d)[0]), "+f"((d)[1]), "+f"((d)[2]), "+f"((d)[3])              \
        : "r"((a)[0]), "r"((a)[1]), "r"((a)[2]), "r"((a)[3]),                 \
          "r"((b)[0]), "r"((b)[1]))

#define MMA_ALL(acc, fa, fb)                                                  \
    _Pragma("unroll")                                                         \
    for (int mf = 0; mf < 4; mf++)                                            \
        _Pragma("unroll")                                                     \
        for (int nf = 0; nf < 4; nf++)                                        \
            MMA_F16(acc[mf][nf], fa[mf], fb[nf])

// ---------------- prep (unchanged) ----------------
__global__ void prep_w_kernel(const float* __restrict__ Wih,
                              const float* __restrict__ Whh,
                              const float* __restrict__ bias) {
    int idx = blockIdx.x * blockDim.x + threadIdx.x;
    if (idx >= G4 * KK) return;
    int p = idx / KK;
    int k = idx % KK;
    int nt = p >> 7, loc = p & 127;
    int wn = loc >> 5, g = (loc >> 3) & 3, hl = loc & 7;
    int h = nt * 32 + wn * 8 + hl;
    int w = g * HH + h;
    float v = (k < INN) ? Wih[(size_t)w * INN + k]
                        : Whh[(size_t)w * HH + (k - INN)];
    g_Wc[idx] = __float2half(v);
    if (idx < HH * 4) {
        int hh = idx >> 2, gg = idx & 3;
        g_bias4[idx] = bias[gg * HH + hh];
    }
}

__global__ void prep_x_kernel(const float* __restrict__ xd) {
    size_t idx = (size_t)blockIdx.x * blockDim.x + threadIdx.x;
    if (idx >= (size_t)TT * Bsz * INN) return;
    int k = (int)(idx & 63);
    int b = (int)((idx >> 6) & 1023);
    int t = (int)(idx >> 16);
    g_x16[idx] = __float2half(xd[(size_t)b * TT * INN + (size_t)t * INN + k]);
}

__global__ void zero_kernel() {
    int idx = blockIdx.x * blockDim.x + threadIdx.x;
    if (idx < Bsz * HH) g_h[0][idx] = __float2half(0.0f);
    if (idx < 8) g_barr[idx] = 0;
}

__device__ __forceinline__ float tanh_ap(float x) {
    float r;
    asm("tanh.approx.f32 %0, %1;" : "=f"(r) : "f"(x));
    return r;
}
__device__ __forceinline__ float sig_ap(float x) {
    return fmaf(0.5f, tanh_ap(0.5f * x), 0.5f);
}

// ---------------- persistent LSTM ----------------
__global__ __launch_bounds__(NTHREADS, 1)
void lstm_persist_kernel() {
    extern __shared__ char smem[];
    const uint32_t sbase = smem_u32(smem);
    const uint32_t BresS = sbase;
    const uint32_t AstgS = sbase + B_RES_B;

    const int tid  = threadIdx.x;
    const int lane = tid & 31;
    const int wid  = tid >> 5;
    const int grp  = lane >> 2;
    const int tig  = lane & 3;
    const int wm   = wid & 1;
    const int wn   = wid >> 1;

    const int nt = blockIdx.x, mt = blockIdx.y;
    const int n0 = nt * BN, b0 = mt * BM;

    // resident B load (once)
#pragma unroll
    for (int i = 0; i < 36; i++) {
        int u = i * NTHREADS + tid;
        int kc  = u >> 10;
        int rem = u & 1023;
        int c = rem >> 3, cq = rem & 7;
        cpa16s(BresS + kc * CHUNK_B + c * 128 + ((cq ^ (c & 7)) << 4),
               g_Wc + (size_t)(n0 + c) * KK + kc * 64 + cq * 8);
    }
    CP_COMMIT();

    const int l7 = lane & 7;
    const uint32_t rAoff = (uint32_t)(wm * 64 + ((lane >> 3) & 1) * 8 + l7) * 128;
    const int kA = (lane >> 4) & 1;
    const uint32_t rBoff = (uint32_t)(wn * 32 + ((lane >> 4) & 1) * 8 + l7) * 128;
    const int kB = (lane >> 3) & 1;
    uint32_t swA[4], swB[4];
#pragma unroll
    for (int ks = 0; ks < 4; ks++) {
        swA[ks] = (uint32_t)(((ks * 2 + kA) ^ l7) << 4);
        swB[ks] = (uint32_t)(((ks * 2 + kB) ^ l7) << 4);
    }

    auto load_x = [&](int t, int stage) {
        uint32_t Ab = AstgS + stage * CHUNK_B;
#pragma unroll
        for (int i = 0; i < 4; i++) {
            int u = i * NTHREADS + tid;
            int r = u >> 3, cq = u & 7;
            cpa16s(Ab + r * 128 + ((cq ^ (r & 7)) << 4),
                   g_x16 + ((size_t)t * Bsz + b0 + r) * INN + cq * 8);
        }
        CP_COMMIT();
    };
    auto load_h = [&](const __half* hp, int kc, int stage) {
        uint32_t Ab = AstgS + stage * CHUNK_B;
#pragma unroll
        for (int i = 0; i < 4; i++) {
            int u = i * NTHREADS + tid;
            int r = u >> 3, cq = u & 7;
            cpa16s(Ab + r * 128 + ((cq ^ (r & 7)) << 4),
                   hp + ((size_t)(b0 + r) << 9) + (kc - 1) * 64 + cq * 8);
        }
        CP_COMMIT();
    };

    auto ldsm_slice = [&](uint32_t Ab, uint32_t Bb, int ks,
                          unsigned (*a)[4], unsigned (*b)[2]) {
#pragma unroll
        for (int mf = 0; mf < 4; mf++)
            LDSM4(a[mf], Ab + rAoff + mf * 2048 + swA[ks]);
        unsigned r01[4], r23[4];
        LDSM4(r01, Bb + rBoff + swB[ks]);
        LDSM4(r23, Bb + rBoff + 2048 + swB[ks]);
        b[0][0] = r01[0]; b[0][1] = r01[1];
        b[1][0] = r01[2]; b[1][1] = r01[3];
        b[2][0] = r23[0]; b[2][1] = r23[1];
        b[3][0] = r23[2]; b[3][1] = r23[3];
    };

    const int qh = nt * 32 + wn * 8 + tig * 2;
    const float4 bg0 = *(const float4*)&g_bias4[qh * 4];
    const float4 bg1 = *(const float4*)&g_bias4[(qh + 1) * 4];

    unsigned fa[3][4][4], fb[3][4][2];
    float acc[4][4][4];
    float creg[4][2][2];
#pragma unroll
    for (int mf = 0; mf < 4; mf++) {
#pragma unroll
        for (int nf = 0; nf < 4; nf++)
#pragma unroll
            for (int r = 0; r < 4; r++) acc[mf][nf][r] = 0.0f;
#pragma unroll
        for (int rr = 0; rr < 2; rr++) {
            creg[mf][rr][0] = 0.0f;
            creg[mf][rr][1] = 0.0f;
        }
    }

    // ---- prologue (t=0): x0 -> stage0, h1..h3 -> stages 1..3 ----
    load_x(0, 0);
    load_h(g_h[0], 1, 1);
    load_h(g_h[0], 2, 2);
    load_h(g_h[0], 3, 3);
    CP_WAIT(3);            // B + x0 complete
    __syncthreads();

    {   // chunk0 of step 0 into acc (gap pattern: bufs 2,0,1,2)
        const uint32_t AbX = AstgS;   // stage 0
        ldsm_slice(AbX, BresS, 0, fa[2], fb[2]);
        ldsm_slice(AbX, BresS, 1, fa[0], fb[0]);
        ldsm_slice(AbX, BresS, 2, fa[1], fb[1]);
        MMA_ALL(acc, fa[2], fb[2]);
        ldsm_slice(AbX, BresS, 3, fa[2], fb[2]);
        MMA_ALL(acc, fa[0], fb[0]);
        MMA_ALL(acc, fa[1], fb[1]);
        MMA_ALL(acc, fa[2], fb[2]);
    }
    CP_WAIT(2);            // h1 complete
    __syncthreads();
    ldsm_slice(AstgS + 1 * CHUNK_B, BresS + CHUNK_B, 0, fa[0], fb[0]);
    ldsm_slice(AstgS + 1 * CHUNK_B, BresS + CHUNK_B, 1, fa[1], fb[1]);

#pragma unroll 1
    for (int t = 0; t < TT; t++) {
        const __half* __restrict__ hprev = g_h[t & 1];
        __half* __restrict__ hnew = g_h[(t & 1) ^ 1];

        // ---- main loop: chunks 1..8 (32 slices), acc already holds chunk0 ----
#pragma unroll
        for (int ki = 0; ki < 8; ki++) {          // chunk = ki+1
            if (ki < 5) {
                load_h(hprev, ki + 4, (t + ki + 4) & 3);
            } else if (ki == 5) {
                load_x(t + 1 < TT ? t + 1 : 0, (t + 1) & 3);
            }
#pragma unroll
            for (int ks = 0; ks < 4; ks++) {
                const int s = 4 * ki + ks;
                const int p = s + 2;
                if (p < 32) {
                    const int kcp = p >> 2;       // chunk index-1 (0..7)
                    const int ksp = p & 3;
                    if (ksp == 0) {
                        if (kcp == 7) CP_WAIT(1); else CP_WAIT(2);
                        __syncthreads();
                    }
                    ldsm_slice(AstgS + ((t + kcp + 1) & 3) * CHUNK_B,
                               BresS + (kcp + 1) * CHUNK_B, ksp,
                               fa[p % 3], fb[p % 3]);
                } else {                          // p = 32, 33 -> x slices 0,1
                    if (p == 32) { CP_WAIT(0); __syncthreads(); }
                    ldsm_slice(AstgS + ((t + 1) & 3) * CHUNK_B,
                               BresS, p - 32, fa[p % 3], fb[p % 3]);
                }
                const int c = s % 3;
                MMA_ALL(acc, fa[c], fb[c]);
            }
        }

        // ---- epilogue ----
#pragma unroll
        for (int mf = 0; mf < 4; mf++) {
#pragma unroll
            for (int rr = 0; rr < 2; rr++) {
                int b = b0 + wm * 64 + mf * 16 + grp + rr * 8;
                size_t cidx = (size_t)b * HH + qh;
                float hh0, hh1;
                {
                    int j = rr * 2 + 0;
                    float zi = acc[mf][0][j] + bg0.x;
                    float zf = acc[mf][1][j] + bg0.y;
                    float zg = acc[mf][2][j] + bg0.z;
                    float zo = acc[mf][3][j] + bg0.w;
                    float cn = fmaf(sig_ap(zf), creg[mf][rr][0], sig_ap(zi) * tanh_ap(zg));
                    creg[mf][rr][0] = cn;
                    hh0 = sig_ap(zo) * tanh_ap(cn);
                }
                {
                    int j = rr * 2 + 1;
                    float zi = acc[mf][0][j] + bg1.x;
                    float zf = acc[mf][1][j] + bg1.y;
                    float zg = acc[mf][2][j] + bg1.z;
                    float zo = acc[mf][3][j] + bg1.w;
                    float cn = fmaf(sig_ap(zf), creg[mf][rr][1], sig_ap(zi) * tanh_ap(zg));
                    creg[mf][rr][1] = cn;
                    hh1 = sig_ap(zo) * tanh_ap(cn);
                }
                *(unsigned*)&hnew[cidx] = h2_as_u32(__floats2half2_rn(hh0, hh1));
            }
        }

        // reset acc for next step
#pragma unroll
        for (int mf = 0; mf < 4; mf++)
#pragma unroll
            for (int nf = 0; nf < 4; nf++)
#pragma unroll
                for (int r = 0; r < 4; r++) acc[mf][nf][r] = 0.0f;

        // ---- barrier arrive, then hide poll under x-chunk MMAs ----
        __threadfence();
        __syncthreads();
        if (tid == 0) atomicAdd(&g_barr[mt], 1u);

        const uint32_t AbX = AstgS + ((t + 1) & 3) * CHUNK_B;
        ldsm_slice(AbX, BresS, 2, fa[1], fb[1]);   // slice34
        MMA_ALL(acc, fa[2], fb[2]);                // slice32
        if (tid == 0) {
            unsigned target = (unsigned)GROUP_CTAS * (unsigned)(t + 1);
            while (*(volatile unsigned*)&g_barr[mt] < target) { }
        }
        ldsm_slice(AbX, BresS, 3, fa[2], fb[2]);   // slice35
        MMA_ALL(acc, fa[0], fb[0]);                // slice33
        MMA_ALL(acc, fa[1], fb[1]);                // slice34
        MMA_ALL(acc, fa[2], fb[2]);                // slice35
        __syncthreads();                           // barrier release visible

        if (t + 1 < TT) {
            const __half* hp2 = g_h[(t + 1) & 1];
            load_h(hp2, 1, (t + 2) & 3);
            load_h(hp2, 2, (t + 3) & 3);
            load_h(hp2, 3, (t + 4) & 3);
            CP_WAIT(2);                 // h1 of t+1 complete
            __syncthreads();
            ldsm_slice(AstgS + ((t + 2) & 3) * CHUNK_B, BresS + CHUNK_B, 0, fa[0], fb[0]);
            ldsm_slice(AstgS + ((t + 2) & 3) * CHUNK_B, BresS + CHUNK_B, 1, fa[1], fb[1]);
        }
    }
}

// out[b] = relu(dot(h_T[b,:], Wl) + bl)
__global__ void head_kernel(const float* __restrict__ Wl,
                            const float* __restrict__ bl,
                            float* __restrict__ out, int sel) {
    int b = blockIdx.x;
    const __half* __restrict__ h = g_h[sel] + (size_t)b * HH;
    float s = 0.0f;
    for (int i = threadIdx.x; i < HH; i += blockDim.x)
        s += __half2float(h[i]) * Wl[i];
#pragma unroll
    for (int o = 16; o; o >>= 1) s += __shfl_down_sync(0xffffffffu, s, o);
    __shared__ float red[8];
    if ((threadIdx.x & 31) == 0) red[threadIdx.x >> 5] = s;
    __syncthreads();
    if (threadIdx.x < 32) {
        s = (threadIdx.x < (blockDim.x >> 5)) ? red[threadIdx.x] : 0.0f;
#pragma unroll
        for (int o = 4; o; o >>= 1) s += __shfl_down_sync(0xffffffffu, s, o);
        if (threadIdx.x == 0) out[b] = fmaxf(s + bl[0], 0.0f);
    }
}

extern "C" void kernel_launch(void* const* d_in, const int* in_sizes, int n_in,
                              void* d_out, int out_size) {
    const float* xd   = (const float*)d_in[0];
    const float* Wih  = (const float*)d_in[1];
    const float* Whh  = (const float*)d_in[2];
    const float* bias = (const float*)d_in[3];
    const float* Wl   = (const float*)d_in[4];
    const float* bl   = (const float*)d_in[5];
    float* out = (float*)d_out;

    cudaFuncSetAttribute(lstm_persist_kernel,
                         cudaFuncAttributeMaxDynamicSharedMemorySize, SMEM_BYTES);

    prep_w_kernel<<<(G4 * KK + 255) / 256, 256>>>(Wih, Whh, bias);
    {
        size_t nx = (size_t)TT * Bsz * INN;
        prep_x_kernel<<<(unsigned)((nx + 255) / 256), 256>>>(xd);
    }
    zero_kernel<<<(Bsz * HH + 255) / 256, 256>>>();

    lstm_persist_kernel<<<dim3(G4 / BN, Bsz / BM), NTHREADS, SMEM_BYTES>>>();

    head_kernel<<<Bsz, 256>>>(Wl, bl, out, 0);
}

// round 17
// speedup vs baseline: 1.1421x; 1.0339x over previous
#include <cuda_runtime.h>
#include <cuda_fp16.h>
#include <math.h>
#include <stdint.h>

#define Bsz 1024
#define TT  730
#define INN 64
#define HH  512
#define KK  576
#define G4  2048

#define BM 128
#define BN 128
#define NCHUNK 9
#define GROUP_CTAS 16
#define NTHREADS 256

#define CHUNK_B 16384
#define B_RES_B (NCHUNK * CHUNK_B)
#define A_STG_B (4 * CHUNK_B)
#define SMEM_BYTES (B_RES_B + A_STG_B)   // 212992

__device__ __half g_Wc[(size_t)G4 * KK];
__device__ float  g_bias4[HH * 4];
__device__ __half g_x16[(size_t)TT * Bsz * INN];
__device__ __half g_h[2][Bsz * HH];
__device__ unsigned g_barr[8];

__device__ __forceinline__ uint32_t smem_u32(const void* p) {
    return (uint32_t)__cvta_generic_to_shared(p);
}
__device__ __forceinline__ void cpa16s(uint32_t dst, const void* src) {
    asm volatile("cp.async.cg.shared.global [%0], [%1], 16;" :: "r"(dst), "l"(src));
}
#define CP_COMMIT() asm volatile("cp.async.commit_group;")
#define CP_WAIT(n)  asm volatile("cp.async.wait_group %0;" :: "n"(n) : "memory")

#define LDSM4(r, a)                                                           \
    asm volatile("ldmatrix.sync.aligned.m8n8.x4.shared.b16 {%0,%1,%2,%3}, [%4];" \
        : "=r"((r)[0]), "=r"((r)[1]), "=r"((r)[2]), "=r"((r)[3]) : "r"(a))

#define MMA_F16(d, a, b)                                                      \
    asm volatile(                                                             \
        "mma.sync.aligned.m16n8k16.row.col.f32.f16.f16.f32 "                  \
        "{%0,%1,%2,%3}, {%4,%5,%6,%7}, {%8,%9}, {%0,%1,%2,%3};"               \
        : "+f"((d)[0]), "+f"((d)[1]), "+f"((d)[2]), "+f"((d)[3])              \
        : "r"((a)[0]), "r"((a)[1]), "r"((a)[2]), "r"((a)[3]),                 \
          "r"((b)[0]), "r"((b)[1]))

#define MMA_ALL(acc, fa, fb)                                                  \
    _Pragma("unroll")                                                         \
    for (int mf = 0; mf < 4; mf++)                                            \
        _Pragma("unroll")                                                     \
        for (int nf = 0; nf < 4; nf++)                                        \
            MMA_F16(acc[mf][nf], fa[mf], fb[nf])

// ---------------- prep ----------------
// o-gate (g==3) weights and bias prescaled by 0.5 for the f16x2 sigmoid path.
__global__ void prep_w_kernel(const float* __restrict__ Wih,
                              const float* __restrict__ Whh,
                              const float* __restrict__ bias) {
    int idx = blockIdx.x * blockDim.x + threadIdx.x;
    if (idx >= G4 * KK) return;
    int p = idx / KK;
    int k = idx % KK;
    int nt = p >> 7, loc = p & 127;
    int wn = loc >> 5, g = (loc >> 3) & 3, hl = loc & 7;
    int h = nt * 32 + wn * 8 + hl;
    int w = g * HH + h;
    float v = (k < INN) ? Wih[(size_t)w * INN + k]
                        : Whh[(size_t)w * HH + (k - INN)];
    if (g == 3) v *= 0.5f;
    g_Wc[idx] = __float2half(v);
    if (idx < HH * 4) {
        int hh = idx >> 2, gg = idx & 3;
        float bv = bias[gg * HH + hh];
        if (gg == 3) bv *= 0.5f;
        g_bias4[idx] = bv;
    }
}

__global__ void prep_x_kernel(const float* __restrict__ xd) {
    size_t idx = (size_t)blockIdx.x * blockDim.x + threadIdx.x;
    if (idx >= (size_t)TT * Bsz * INN) return;
    int k = (int)(idx & 63);
    int b = (int)((idx >> 6) & 1023);
    int t = (int)(idx >> 16);
    g_x16[idx] = __float2half(xd[(size_t)b * TT * INN + (size_t)t * INN + k]);
}

__global__ void zero_kernel() {
    int idx = blockIdx.x * blockDim.x + threadIdx.x;
    if (idx < Bsz * HH) g_h[0][idx] = __float2half(0.0f);
    if (idx < 8) g_barr[idx] = 0;
}

__device__ __forceinline__ float tanh_ap(float x) {
    float r;
    asm("tanh.approx.f32 %0, %1;" : "=f"(r) : "f"(x));
    return r;
}
__device__ __forceinline__ float sig_ap(float x) {
    return fmaf(0.5f, tanh_ap(0.5f * x), 0.5f);
}
__device__ __forceinline__ uint32_t packh2(float lo, float hi) {
    uint32_t r;
    asm("cvt.rn.f16x2.f32 %0, %1, %2;" : "=r"(r) : "f"(hi), "f"(lo));
    return r;
}
__device__ __forceinline__ uint32_t tanh2_ap(uint32_t x) {
    uint32_t r;
    asm("tanh.approx.f16x2 %0, %1;" : "=r"(r) : "r"(x));
    return r;
}
__device__ __forceinline__ uint32_t hfma2u(uint32_t a, uint32_t b, uint32_t c) {
    uint32_t r;
    asm("fma.rn.f16x2 %0, %1, %2, %3;" : "=r"(r) : "r"(a), "r"(b), "r"(c));
    return r;
}
__device__ __forceinline__ uint32_t hmul2u(uint32_t a, uint32_t b) {
    uint32_t r;
    asm("mul.rn.f16x2 %0, %1, %2;" : "=r"(r) : "r"(a), "r"(b));
    return r;
}

// ---------------- persistent LSTM ----------------
__global__ __launch_bounds__(NTHREADS, 1)
void lstm_persist_kernel() {
    extern __shared__ char smem[];
    const uint32_t sbase = smem_u32(smem);
    const uint32_t BresS = sbase;
    const uint32_t AstgS = sbase + B_RES_B;

    const int tid  = threadIdx.x;
    const int lane = tid & 31;
    const int wid  = tid >> 5;
    const int grp  = lane >> 2;
    const int tig  = lane & 3;
    const int wm   = wid & 1;
    const int wn   = wid >> 1;

    const int nt = blockIdx.x, mt = blockIdx.y;
    const int n0 = nt * BN, b0 = mt * BM;

#pragma unroll
    for (int i = 0; i < 36; i++) {
        int u = i * NTHREADS + tid;
        int kc  = u >> 10;
        int rem = u & 1023;
        int c = rem >> 3, cq = rem & 7;
        cpa16s(BresS + kc * CHUNK_B + c * 128 + ((cq ^ (c & 7)) << 4),
               g_Wc + (size_t)(n0 + c) * KK + kc * 64 + cq * 8);
    }
    CP_COMMIT();

    const int l7 = lane & 7;
    const uint32_t rAoff = (uint32_t)(wm * 64 + ((lane >> 3) & 1) * 8 + l7) * 128;
    const int kA = (lane >> 4) & 1;
    const uint32_t rBoff = (uint32_t)(wn * 32 + ((lane >> 4) & 1) * 8 + l7) * 128;
    const int kB = (lane >> 3) & 1;
    uint32_t swA[4], swB[4];
#pragma unroll
    for (int ks = 0; ks < 4; ks++) {
        swA[ks] = (uint32_t)(((ks * 2 + kA) ^ l7) << 4);
        swB[ks] = (uint32_t)(((ks * 2 + kB) ^ l7) << 4);
    }

    auto load_x = [&](int t, int stage) {
        uint32_t Ab = AstgS + stage * CHUNK_B;
#pragma unroll
        for (int i = 0; i < 4; i++) {
            int u = i * NTHREADS + tid;
            int r = u >> 3, cq = u & 7;
            cpa16s(Ab + r * 128 + ((cq ^ (r & 7)) << 4),
                   g_x16 + ((size_t)t * Bsz + b0 + r) * INN + cq * 8);
        }
        CP_COMMIT();
    };
    auto load_h = [&](const __half* hp, int kc, int stage) {
        uint32_t Ab = AstgS + stage * CHUNK_B;
#pragma unroll
        for (int i = 0; i < 4; i++) {
            int u = i * NTHREADS + tid;
            int r = u >> 3, cq = u & 7;
            cpa16s(Ab + r * 128 + ((cq ^ (r & 7)) << 4),
                   hp + ((size_t)(b0 + r) << 9) + (kc - 1) * 64 + cq * 8);
        }
        CP_COMMIT();
    };

    auto ldsm_slice = [&](uint32_t Ab, uint32_t Bb, int ks,
                          unsigned (*a)[4], unsigned (*b)[2]) {
#pragma unroll
        for (int mf = 0; mf < 4; mf++)
            LDSM4(a[mf], Ab + rAoff + mf * 2048 + swA[ks]);
        unsigned r01[4], r23[4];
        LDSM4(r01, Bb + rBoff + swB[ks]);
        LDSM4(r23, Bb + rBoff + 2048 + swB[ks]);
        b[0][0] = r01[0]; b[0][1] = r01[1];
        b[1][0] = r01[2]; b[1][1] = r01[3];
        b[2][0] = r23[0]; b[2][1] = r23[1];
        b[3][0] = r23[2]; b[3][1] = r23[3];
    };

    const int qh = nt * 32 + wn * 8 + tig * 2;
    const float4 bg0 = *(const float4*)&g_bias4[qh * 4];
    const float4 bg1 = *(const float4*)&g_bias4[(qh + 1) * 4];
    const uint32_t half2_half = 0x38003800u;   // {0.5h, 0.5h}

    unsigned fa[3][4][4], fb[3][4][2];
    float acc[4][4][4];
    float creg[4][2][2];
#pragma unroll
    for (int mf = 0; mf < 4; mf++) {
#pragma unroll
        for (int nf = 0; nf < 4; nf++)
#pragma unroll
            for (int r = 0; r < 4; r++) acc[mf][nf][r] = 0.0f;
#pragma unroll
        for (int rr = 0; rr < 2; rr++) {
            creg[mf][rr][0] = 0.0f;
            creg[mf][rr][1] = 0.0f;
        }
    }

    // prologue (t=0)
    load_x(0, 0);
    load_h(g_h[0], 1, 1);
    load_h(g_h[0], 2, 2);
    load_h(g_h[0], 3, 3);
    CP_WAIT(3);
    __syncthreads();

    {   // chunk0 of step 0 into acc
        const uint32_t AbX = AstgS;
        ldsm_slice(AbX, BresS, 0, fa[2], fb[2]);
        ldsm_slice(AbX, BresS, 1, fa[0], fb[0]);
        ldsm_slice(AbX, BresS, 2, fa[1], fb[1]);
        MMA_ALL(acc, fa[2], fb[2]);
        ldsm_slice(AbX, BresS, 3, fa[2], fb[2]);
        MMA_ALL(acc, fa[0], fb[0]);
        MMA_ALL(acc, fa[1], fb[1]);
        MMA_ALL(acc, fa[2], fb[2]);
    }
    CP_WAIT(2);
    __syncthreads();
    ldsm_slice(AstgS + 1 * CHUNK_B, BresS + CHUNK_B, 0, fa[0], fb[0]);
    ldsm_slice(AstgS + 1 * CHUNK_B, BresS + CHUNK_B, 1, fa[1], fb[1]);

#pragma unroll 1
    for (int t = 0; t < TT; t++) {
        const __half* __restrict__ hprev = g_h[t & 1];
        __half* __restrict__ hnew = g_h[(t & 1) ^ 1];

        // ---- main loop: chunks 1..8 ----
#pragma unroll
        for (int ki = 0; ki < 8; ki++) {
            if (ki < 5) {
                load_h(hprev, ki + 4, (t + ki + 4) & 3);
            } else if (ki == 5) {
                load_x(t + 1 < TT ? t + 1 : 0, (t + 1) & 3);
            }
#pragma unroll
            for (int ks = 0; ks < 4; ks++) {
                const int s = 4 * ki + ks;
                const int p = s + 2;
                if (p < 32) {
                    const int kcp = p >> 2;
                    const int ksp = p & 3;
                    if (ksp == 0) {
                        if (kcp == 7) CP_WAIT(1); else CP_WAIT(2);
                        __syncthreads();
                    }
                    ldsm_slice(AstgS + ((t + kcp + 1) & 3) * CHUNK_B,
                               BresS + (kcp + 1) * CHUNK_B, ksp,
                               fa[p % 3], fb[p % 3]);
                } else {
                    if (p == 32) { CP_WAIT(0); __syncthreads(); }
                    ldsm_slice(AstgS + ((t + 1) & 3) * CHUNK_B,
                               BresS, p - 32, fa[p % 3], fb[p % 3]);
                }
                const int c = s % 3;
                MMA_ALL(acc, fa[c], fb[c]);
            }
        }

        // ---- epilogue: i,f,g fp32; o + tanh(c) in f16x2 ----
#pragma unroll
        for (int mf = 0; mf < 4; mf++) {
#pragma unroll
            for (int rr = 0; rr < 2; rr++) {
                int b = b0 + wm * 64 + mf * 16 + grp + rr * 8;
                size_t cidx = (size_t)b * HH + qh;
                const int j0 = rr * 2, j1 = rr * 2 + 1;
                float zi0 = acc[mf][0][j0] + bg0.x;
                float zf0 = acc[mf][1][j0] + bg0.y;
                float zg0 = acc[mf][2][j0] + bg0.z;
                float zo0 = acc[mf][3][j0] + bg0.w;   // prescaled 0.5*z_o
                float zi1 = acc[mf][0][j1] + bg1.x;
                float zf1 = acc[mf][1][j1] + bg1.y;
                float zg1 = acc[mf][2][j1] + bg1.z;
                float zo1 = acc[mf][3][j1] + bg1.w;
                float cn0 = fmaf(sig_ap(zf0), creg[mf][rr][0],
                                 sig_ap(zi0) * tanh_ap(zg0));
                float cn1 = fmaf(sig_ap(zf1), creg[mf][rr][1],
                                 sig_ap(zi1) * tanh_ap(zg1));
                creg[mf][rr][0] = cn0;
                creg[mf][rr][1] = cn1;
                uint32_t o2  = hfma2u(tanh2_ap(packh2(zo0, zo1)),
                                      half2_half, half2_half);
                uint32_t tc2 = tanh2_ap(packh2(cn0, cn1));
                *(uint32_t*)&hnew[cidx] = hmul2u(o2, tc2);
            }
        }

        // reset acc
#pragma unroll
        for (int mf = 0; mf < 4; mf++)
#pragma unroll
            for (int nf = 0; nf < 4; nf++)
#pragma unroll
                for (int r = 0; r < 4; r++) acc[mf][nf][r] = 0.0f;

        // ---- barrier: arrive, hide poll under s32, release, issue h loads,
        //      hide h1 latency under s33-35 ----
        __threadfence();
        __syncthreads();
        if (tid == 0) atomicAdd(&g_barr[mt], 1u);

        MMA_ALL(acc, fa[2], fb[2]);                // slice32
        if (tid == 0) {
            unsigned target = (unsigned)GROUP_CTAS * (unsigned)(t + 1);
            while (*(volatile unsigned*)&g_barr[mt] < target) { }
        }
        __syncthreads();                           // release

        if (t + 1 < TT) {
            const __half* hp2 = g_h[(t + 1) & 1];
            load_h(hp2, 1, (t + 2) & 3);           // issue NOW; covered below
            load_h(hp2, 2, (t + 3) & 3);
            load_h(hp2, 3, (t + 4) & 3);
        }

        const uint32_t AbX = AstgS + ((t + 1) & 3) * CHUNK_B;
        ldsm_slice(AbX, BresS, 2, fa[1], fb[1]);   // slice34
        MMA_ALL(acc, fa[0], fb[0]);                // slice33
        ldsm_slice(AbX, BresS, 3, fa[2], fb[2]);   // slice35
        MMA_ALL(acc, fa[1], fb[1]);                // slice34
        MMA_ALL(acc, fa[2], fb[2]);                // slice35

        CP_WAIT(2);                                // h1 of t+1 complete
        __syncthreads();
        ldsm_slice(AstgS + ((t + 2) & 3) * CHUNK_B, BresS + CHUNK_B, 0, fa[0], fb[0]);
        ldsm_slice(AstgS + ((t + 2) & 3) * CHUNK_B, BresS + CHUNK_B, 1, fa[1], fb[1]);
    }
}

// out[b] = relu(dot(h_T[b,:], Wl) + bl)
__global__ void head_kernel(const float* __restrict__ Wl,
                            const float* __restrict__ bl,
                            float* __restrict__ out, int sel) {
    int b = blockIdx.x;
    const __half* __restrict__ h = g_h[sel] + (size_t)b * HH;
    float s = 0.0f;
    for (int i = threadIdx.x; i < HH; i += blockDim.x)
        s += __half2float(h[i]) * Wl[i];
#pragma unroll
    for (int o = 16; o; o >>= 1) s += __shfl_down_sync(0xffffffffu, s, o);
    __shared__ float red[8];
    if ((threadIdx.x & 31) == 0) red[threadIdx.x >> 5] = s;
    __syncthreads();
    if (threadIdx.x < 32) {
        s = (threadIdx.x < (blockDim.x >> 5)) ? red[threadIdx.x] : 0.0f;
#pragma unroll
        for (int o = 4; o; o >>= 1) s += __shfl_down_sync(0xffffffffu, s, o);
        if (threadIdx.x == 0) out[b] = fmaxf(s + bl[0], 0.0f);
    }
}

extern "C" void kernel_launch(void* const* d_in, const int* in_sizes, int n_in,
                              void* d_out, int out_size) {
    const float* xd   = (const float*)d_in[0];
    const float* Wih  = (const float*)d_in[1];
    const float* Whh  = (const float*)d_in[2];
    const float* bias = (const float*)d_in[3];
    const float* Wl   = (const float*)d_in[4];
    const float* bl   = (const float*)d_in[5];
    float* out = (float*)d_out;

    cudaFuncSetAttribute(lstm_persist_kernel,
                         cudaFuncAttributeMaxDynamicSharedMemorySize, SMEM_BYTES);

    prep_w_kernel<<<(G4 * KK + 255) / 256, 256>>>(Wih, Whh, bias);
    {
        size_t nx = (size_t)TT * Bsz * INN;
        prep_x_kernel<<<(unsigned)((nx + 255) / 256), 256>>>(xd);
    }
    zero_kernel<<<(Bsz * HH + 255) / 256, 256>>>();

    lstm_persist_kernel<<<dim3(G4 / BN, Bsz / BM), NTHREADS, SMEM_BYTES>>>();

    head_kernel<<<Bsz, 256>>>(Wl, bl, out, 0);
}